// round 12
// baseline (speedup 1.0000x reference)
#include <cuda_runtime.h>
#include <cuda_fp16.h>
#include <math.h>
#include <stdint.h>

#define H_DIM 4096
#define E_DIM 64
#define TOPK  8
#define BM    128                 // tokens per CTA (96 tensor + 32 ffma)
#define KC    64                  // K per chunk (= one accumulation segment)
#define NCHUNK (H_DIM / KC)       // 64
#define THREADS 512

#define TROWS 96                  // tensor-path rows per CTA
#define FROWS 32                  // ffma-path rows per CTA

#define A_PL  (TROWS * KC * 2)    // 12288 B per A fp16 plane
#define B_PL  (E_DIM * KC * 2)    // 8192  B per B fp16 plane
#define AF_STR 36                 // floats per Af row (k-major [KC][AF_STR])
#define WF_STR 66                 // floats per Wf row (k-major [KC][WF_STR])
#define AF_SZ (KC * AF_STR * 4)   // 9216 B
#define WF_SZ (KC * WF_STR * 4)   // 16896 B
// stage offsets
#define OFF_AH 0
#define OFF_AL (OFF_AH + A_PL)
#define OFF_BH (OFF_AL + A_PL)
#define OFF_BL (OFF_BH + B_PL)
#define OFF_AF (OFF_BL + B_PL)
#define OFF_WF (OFF_AF + AF_SZ)
#define STAGE_SZ (OFF_WF + WF_SZ)        // 67072 B
#define TILE_SZ (2 * STAGE_SZ)           // 134144 B
#define LT_STR 66                        // topk smem logits row stride (floats)
#define DYN_SZ (TILE_SZ + 256)

#define W_SCALE   64.0f           // W pre-scale for fp16 planes (2^6, exact)
#define OUT_SCALE 0.015625f       // 2^-6
#define LO_SCALE  2048.0f         // lo-plane pre-scale (2^11, exact)
#define LO_FOLD   4.8828125e-4f   // 2^-11

typedef unsigned long long u64;

__device__ __forceinline__ uint32_t s2u(const void* p) {
    uint32_t a;
    asm("{ .reg .u64 t; cvta.to.shared.u64 t, %1; cvt.u32.u64 %0, t; }" : "=r"(a) : "l"(p));
    return a;
}
__device__ __forceinline__ uint32_t swz(uint32_t b) { return b ^ ((b >> 3) & 0x70); }

__device__ __forceinline__ void fma2(u64& d, u64 a, u64 b) {
    asm("fma.rn.f32x2 %0, %1, %2, %0;" : "+l"(d) : "l"(a), "l"(b));
}
__device__ __forceinline__ u64 add2(u64 a, u64 b) {
    u64 r;
    asm("add.rn.f32x2 %0, %1, %2;" : "=l"(r) : "l"(a), "l"(b));
    return r;
}
__device__ __forceinline__ u64 pk2(float x) {
    u64 r;
    asm("mov.b64 %0, {%1, %1};" : "=l"(r) : "f"(x));
    return r;
}
__device__ __forceinline__ void upk(u64 v, float& lo, float& hi) {
    asm("mov.b64 {%0, %1}, %2;" : "=f"(lo), "=f"(hi) : "l"(v));
}
__device__ __forceinline__ float lds_f32(uint32_t a) {
    float v;
    asm volatile("ld.shared.b32 %0, [%1];" : "=f"(v) : "r"(a));
    return v;
}
__device__ __forceinline__ u64 lds_u64(uint32_t a) {
    u64 v;
    asm volatile("ld.shared.b64 %0, [%1];" : "=l"(v) : "r"(a));
    return v;
}

// fp16 2-way split of one float4 (verified R11)
__device__ __forceinline__ void cvt_store2(float4 v, float scale,
                                           uint32_t hB, uint32_t lB, int row, int c4) {
    v.x *= scale; v.y *= scale; v.z *= scale; v.w *= scale;
    uint32_t h01, h23;
    asm("cvt.rn.f16x2.f32 %0, %1, %2;" : "=r"(h01) : "f"(v.y), "f"(v.x));
    asm("cvt.rn.f16x2.f32 %0, %1, %2;" : "=r"(h23) : "f"(v.w), "f"(v.z));
    float h0, h1, h2, h3;
    asm("{.reg .b16 lo,hi; mov.b32 {lo,hi}, %2; cvt.f32.f16 %0, lo; cvt.f32.f16 %1, hi;}"
        : "=f"(h0), "=f"(h1) : "r"(h01));
    asm("{.reg .b16 lo,hi; mov.b32 {lo,hi}, %2; cvt.f32.f16 %0, lo; cvt.f32.f16 %1, hi;}"
        : "=f"(h2), "=f"(h3) : "r"(h23));
    float r0 = (v.x - h0) * LO_SCALE, r1 = (v.y - h1) * LO_SCALE;
    float r2 = (v.z - h2) * LO_SCALE, r3 = (v.w - h3) * LO_SCALE;
    uint32_t l01, l23;
    asm("cvt.rn.f16x2.f32 %0, %1, %2;" : "=r"(l01) : "f"(r1), "f"(r0));
    asm("cvt.rn.f16x2.f32 %0, %1, %2;" : "=r"(l23) : "f"(r3), "f"(r2));
    uint32_t off = swz((uint32_t)(row * 128 + c4 * 8));
    asm volatile("st.shared.v2.b32 [%0], {%1,%2};" :: "r"(hB + off), "r"(h01), "r"(h23));
    asm volatile("st.shared.v2.b32 [%0], {%1,%2};" :: "r"(lB + off), "r"(l01), "r"(l23));
}

__device__ __forceinline__ void ldsm4(uint32_t addr, uint32_t& r0, uint32_t& r1,
                                      uint32_t& r2, uint32_t& r3) {
    asm volatile("ldmatrix.sync.aligned.m8n8.x4.shared.b16 {%0,%1,%2,%3}, [%4];"
                 : "=r"(r0), "=r"(r1), "=r"(r2), "=r"(r3) : "r"(addr));
}

__device__ __forceinline__ void mma16816(float* d, const uint32_t* a, const uint32_t* b) {
    asm volatile(
        "mma.sync.aligned.m16n8k16.row.col.f32.f16.f16.f32 "
        "{%0,%1,%2,%3}, {%4,%5,%6,%7}, {%8,%9}, {%0,%1,%2,%3};"
        : "+f"(d[0]), "+f"(d[1]), "+f"(d[2]), "+f"(d[3])
        : "r"(a[0]), "r"(a[1]), "r"(a[2]), "r"(a[3]), "r"(b[0]), "r"(b[1]));
}

// ---------------------------------------------------------------------------
// Fused router: GEMM (tensor rows 0-95 fp16-split / ffma rows 96-127 fp32)
// + top-8 softmax scores, one kernel.
// ---------------------------------------------------------------------------
__global__ __launch_bounds__(THREADS, 1) void router_fused(
    const float* __restrict__ A, const float* __restrict__ W,
    float* __restrict__ logits, float* __restrict__ scores,
    float* __restrict__ indices)
{
    extern __shared__ char dsm[];
    const uint32_t base = (s2u(dsm) + 127u) & ~127u;
    const uint32_t stage_base[2] = { base, base + STAGE_SZ };

    const int tid  = threadIdx.x;
    const int warp = tid >> 5;
    const int lane = tid & 31;
    const int m0   = blockIdx.x * BM;

    // ---- staging register loads ----
    float4 na[3], naf, nb[2];
    {
        #pragma unroll
        for (int i = 0; i < 3; i++) {              // tensor A rows 0..95
            int idx = tid + i * THREADS;           // 0..1535
            na[i] = *reinterpret_cast<const float4*>(
                A + (size_t)(m0 + (idx >> 4)) * H_DIM + (idx & 15) * 4);
        }
        naf = *reinterpret_cast<const float4*>(    // ffma A rows 96..127
            A + (size_t)(m0 + TROWS + (tid >> 4)) * H_DIM + (tid & 15) * 4);
        #pragma unroll
        for (int i = 0; i < 2; i++) {              // W rows 0..63
            int idx = tid + i * THREADS;           // 0..1023
            nb[i] = *reinterpret_cast<const float4*>(
                W + (size_t)(idx >> 4) * H_DIM + (idx & 15) * 4);
        }
    }

    // tensor-warp fragment mapping (warps 0..11)
    const int rg = warp >> 1;                      // 0..5
    const int eh = warp & 1;
    const uint32_t a_off0 = (uint32_t)((rg * 16 + (lane & 15)) * 128 + (lane >> 4) * 16);
    const uint32_t b_off0 = (uint32_t)((((lane >> 4) << 3) + (lane & 7)) * 128 +
                                       ((lane >> 3) & 1) * 16 + eh * 2 * 2048);

    float accM[4][4];
    #pragma unroll
    for (int nt = 0; nt < 4; nt++)
        #pragma unroll
        for (int j = 0; j < 4; j++) accM[nt][j] = 0.f;

    // ffma-warp mapping (warps 12..15)
    const int fw  = warp - 12;
    const int rl1 = fw * 8 + (lane >> 3);          // local ffma rows (0..31)
    const int rl2 = rl1 + 4;
    const int cb  = (lane & 7) * 8;                // col base
    u64 accF[2][4];
    #pragma unroll
    for (int r = 0; r < 2; r++)
        #pragma unroll
        for (int p = 0; p < 4; p++) accF[r][p] = 0ull;

    for (int chunk = 0; chunk < NCHUNK; ++chunk) {
        const int s = chunk & 1;
        const uint32_t st = stage_base[s];
        const uint32_t aH = st + OFF_AH, aL = st + OFF_AL;
        const uint32_t bH = st + OFF_BH, bL = st + OFF_BL;
        const uint32_t af = st + OFF_AF, wf = st + OFF_WF;

        // ---- convert + store current staged regs ----
        #pragma unroll
        for (int i = 0; i < 3; i++) {
            int idx = tid + i * THREADS;
            cvt_store2(na[i], 1.0f, aH, aL, idx >> 4, idx & 15);
        }
        {   // ffma A fp32, k-major
            int row = tid >> 4, c4 = tid & 15;
            float v[4] = {naf.x, naf.y, naf.z, naf.w};
            #pragma unroll
            for (int j = 0; j < 4; j++)
                asm volatile("st.shared.b32 [%0], %1;"
                             :: "r"(af + (uint32_t)(((c4 * 4 + j) * AF_STR + row) * 4)),
                                "f"(v[j]));
        }
        #pragma unroll
        for (int i = 0; i < 2; i++) {
            int idx = tid + i * THREADS;
            int row = idx >> 4, c4 = idx & 15;
            cvt_store2(nb[i], W_SCALE, bH, bL, row, c4);
            float v[4] = {nb[i].x, nb[i].y, nb[i].z, nb[i].w};
            #pragma unroll
            for (int j = 0; j < 4; j++)
                asm volatile("st.shared.b32 [%0], %1;"
                             :: "r"(wf + (uint32_t)(((c4 * 4 + j) * WF_STR + row) * 4)),
                                "f"(v[j]));
        }
        // ---- prefetch next chunk ----
        if (chunk + 1 < NCHUNK) {
            const int k0 = (chunk + 1) * KC;
            #pragma unroll
            for (int i = 0; i < 3; i++) {
                int idx = tid + i * THREADS;
                na[i] = *reinterpret_cast<const float4*>(
                    A + (size_t)(m0 + (idx >> 4)) * H_DIM + k0 + (idx & 15) * 4);
            }
            naf = *reinterpret_cast<const float4*>(
                A + (size_t)(m0 + TROWS + (tid >> 4)) * H_DIM + k0 + (tid & 15) * 4);
            #pragma unroll
            for (int i = 0; i < 2; i++) {
                int idx = tid + i * THREADS;
                nb[i] = *reinterpret_cast<const float4*>(
                    W + (size_t)(idx >> 4) * H_DIM + k0 + (idx & 15) * 4);
            }
        }
        __syncthreads();

        if (warp < 12) {
            // ---- tensor path (verified R11 mainloop) ----
            float accS0[4][4], accS1[4][4];
            #pragma unroll
            for (int nt = 0; nt < 4; nt++)
                #pragma unroll
                for (int j = 0; j < 4; j++) { accS0[nt][j] = 0.f; accS1[nt][j] = 0.f; }

            #pragma unroll
            for (int ks = 0; ks < 4; ks++) {
                const uint32_t ka = (uint32_t)(ks * 32);
                uint32_t ah[4], al[4];
                ldsm4(aH + swz(a_off0 + ka), ah[0], ah[1], ah[2], ah[3]);
                ldsm4(aL + swz(a_off0 + ka), al[0], al[1], al[2], al[3]);

                uint32_t bf[4][2];
                const uint32_t bo0 = swz(b_off0 + ka);
                const uint32_t bo1 = swz(b_off0 + 2048 + ka);

                ldsm4(bH + bo0, bf[0][0], bf[0][1], bf[1][0], bf[1][1]);
                ldsm4(bH + bo1, bf[2][0], bf[2][1], bf[3][0], bf[3][1]);
                #pragma unroll
                for (int nt = 0; nt < 4; nt++) mma16816(accS0[nt], ah, bf[nt]);
                #pragma unroll
                for (int nt = 0; nt < 4; nt++) mma16816(accS1[nt], al, bf[nt]);

                ldsm4(bL + bo0, bf[0][0], bf[0][1], bf[1][0], bf[1][1]);
                ldsm4(bL + bo1, bf[2][0], bf[2][1], bf[3][0], bf[3][1]);
                #pragma unroll
                for (int nt = 0; nt < 4; nt++) mma16816(accS1[nt], ah, bf[nt]);
            }
            #pragma unroll
            for (int nt = 0; nt < 4; nt++)
                #pragma unroll
                for (int j = 0; j < 4; j++)
                    accM[nt][j] += fmaf(accS1[nt][j], LO_FOLD, accS0[nt][j]);
        } else {
            // ---- ffma path: rows 96-127, chunked serial fp32 RN ----
            u64 accC[2][4];
            #pragma unroll
            for (int r = 0; r < 2; r++)
                #pragma unroll
                for (int p = 0; p < 4; p++) accC[r][p] = 0ull;

            uint32_t afp = af + (uint32_t)(rl1 * 4);
            uint32_t wfp = wf + (uint32_t)(cb * 4);
            #pragma unroll 8
            for (int k = 0; k < KC; k++) {
                u64 A1 = pk2(lds_f32(afp));
                u64 A2 = pk2(lds_f32(afp + (uint32_t)((rl2 - rl1) * 4)));
                u64 w0 = lds_u64(wfp);
                u64 w1 = lds_u64(wfp + 8);
                u64 w2 = lds_u64(wfp + 16);
                u64 w3 = lds_u64(wfp + 24);
                fma2(accC[0][0], A1, w0); fma2(accC[0][1], A1, w1);
                fma2(accC[0][2], A1, w2); fma2(accC[0][3], A1, w3);
                fma2(accC[1][0], A2, w0); fma2(accC[1][1], A2, w1);
                fma2(accC[1][2], A2, w2); fma2(accC[1][3], A2, w3);
                afp += AF_STR * 4;
                wfp += WF_STR * 4;
            }
            #pragma unroll
            for (int r = 0; r < 2; r++)
                #pragma unroll
                for (int p = 0; p < 4; p++) accF[r][p] = add2(accF[r][p], accC[r][p]);
        }
    }

    // ---- epilogue: write logits (gmem + smem) ----
    const uint32_t LT = base;                 // alias stage0 (free after last chunk)
    if (warp < 12) {
        const int lr0 = rg * 16 + (lane >> 2);        // local row
        const int col = eh * 32 + (lane & 3) * 2;
        #pragma unroll
        for (int nt = 0; nt < 4; nt++) {
            float v0 = accM[nt][0] * OUT_SCALE, v1 = accM[nt][1] * OUT_SCALE;
            float v2 = accM[nt][2] * OUT_SCALE, v3 = accM[nt][3] * OUT_SCALE;
            const int c = nt * 8 + col;
            *reinterpret_cast<float2*>(logits + (size_t)(m0 + lr0) * E_DIM + c) =
                make_float2(v0, v1);
            *reinterpret_cast<float2*>(logits + (size_t)(m0 + lr0 + 8) * E_DIM + c) =
                make_float2(v2, v3);
            asm volatile("st.shared.v2.b32 [%0], {%1,%2};"
                         :: "r"(LT + (uint32_t)((lr0 * LT_STR + c) * 4)),
                            "r"(__float_as_uint(v0)), "r"(__float_as_uint(v1)));
            asm volatile("st.shared.v2.b32 [%0], {%1,%2};"
                         :: "r"(LT + (uint32_t)(((lr0 + 8) * LT_STR + c) * 4)),
                            "r"(__float_as_uint(v2)), "r"(__float_as_uint(v3)));
        }
    } else {
        #pragma unroll
        for (int r = 0; r < 2; r++) {
            const int lrow = TROWS + (r == 0 ? rl1 : rl2);
            #pragma unroll
            for (int p = 0; p < 4; p++) {
                float lo, hi;
                upk(accF[r][p], lo, hi);
                const int c = cb + p * 2;
                *reinterpret_cast<float2*>(logits + (size_t)(m0 + lrow) * E_DIM + c) =
                    make_float2(lo, hi);
                asm volatile("st.shared.v2.b32 [%0], {%1,%2};"
                             :: "r"(LT + (uint32_t)((lrow * LT_STR + c) * 4)),
                                "r"(__float_as_uint(lo)), "r"(__float_as_uint(hi)));
            }
        }
    }
    __syncthreads();

    // ---- fused top-8 + renormalized softmax (verified algorithm, smem input) ----
    #pragma unroll 1
    for (int t = 0; t < 8; t++) {
        const int row = warp * 8 + t;
        const uint32_t lg = LT + (uint32_t)(row * LT_STR * 4);
        float v0 = lds_f32(lg + (uint32_t)(lane * 4));
        float v1 = lds_f32(lg + (uint32_t)((lane + 32) * 4));

        float topv[TOPK];
        int   topi[TOPK];
        #pragma unroll
        for (int r = 0; r < TOPK; r++) {
            bool p   = (v0 >= v1);
            float lv = p ? v0 : v1;
            int   li = p ? lane : lane + 32;
            #pragma unroll
            for (int off = 16; off > 0; off >>= 1) {
                float ov = __shfl_xor_sync(0xffffffffu, lv, off);
                int   oi = __shfl_xor_sync(0xffffffffu, li, off);
                if (ov > lv || (ov == lv && oi < li)) { lv = ov; li = oi; }
            }
            topv[r] = lv; topi[r] = li;
            if (li == lane)           v0 = -INFINITY;
            else if (li == lane + 32) v1 = -INFINITY;
        }
        if (lane == 0) {
            const float m = topv[0];
            float e[TOPK], ssum = 0.f;
            #pragma unroll
            for (int r = 0; r < TOPK; r++) { e[r] = expf(topv[r] - m); ssum += e[r]; }
            const float inv = 1.f / ssum;
            #pragma unroll
            for (int r = 0; r < TOPK; r++) {
                scores [(size_t)(m0 + row) * TOPK + r] = e[r] * inv;
                indices[(size_t)(m0 + row) * TOPK + r] = (float)topi[r];
            }
        }
    }
}

// ---------------------------------------------------------------------------
extern "C" void kernel_launch(void* const* d_in, const int* in_sizes, int n_in,
                              void* d_out, int out_size)
{
    const float* hs = (const float*)d_in[0];   // hidden_states [T, 4096]
    const float* w  = (const float*)d_in[1];   // weight        [64, 4096]
    const int T = in_sizes[0] / H_DIM;

    float* out     = (float*)d_out;
    float* logits  = out;
    float* scores  = out + (size_t)T * E_DIM;
    float* indices = scores + (size_t)T * TOPK;

    cudaFuncSetAttribute(router_fused, cudaFuncAttributeMaxDynamicSharedMemorySize, DYN_SZ);
    router_fused<<<T / BM, THREADS, DYN_SZ>>>(hs, w, logits, scores, indices);
}

// round 13
// speedup vs baseline: 2.2772x; 2.2772x over previous
#include <cuda_runtime.h>
#include <cuda_fp16.h>
#include <math.h>
#include <stdint.h>

#define H_DIM 4096
#define E_DIM 64
#define TOPK  8
#define BM    128                 // tokens per CTA
#define KC    64                  // K per chunk (= one accumulation segment)
#define NCHUNK (H_DIM / KC)       // 64
#define THREADS 512

#define A_PL  (BM * KC * 2)       // 16384 B per A fp16 plane
#define B_PL  (E_DIM * KC * 2)    // 8192  B per B fp16 plane
#define STAGE_SZ (2 * A_PL + 2 * B_PL)   // 49152 B
#define TILE_SZ (2 * STAGE_SZ)           // 98304 B
#define LT_STR 66                        // fused-topk smem logits row stride (floats)
#define DYN_SZ (TILE_SZ + 256)

#define W_SCALE   64.0f           // W pre-scale (2^6, exact)
#define OUT_SCALE 0.015625f       // 2^-6
#define LO_SCALE  2048.0f         // lo-plane pre-scale (2^11, exact)
#define LO_FOLD   4.8828125e-4f   // 2^-11

__device__ __forceinline__ uint32_t s2u(const void* p) {
    uint32_t a;
    asm("{ .reg .u64 t; cvta.to.shared.u64 t, %1; cvt.u32.u64 %0, t; }" : "=r"(a) : "l"(p));
    return a;
}
__device__ __forceinline__ uint32_t swz(uint32_t b) { return b ^ ((b >> 3) & 0x70); }
__device__ __forceinline__ float lds_f32(uint32_t a) {
    float v;
    asm volatile("ld.shared.b32 %0, [%1];" : "=f"(v) : "r"(a));
    return v;
}

// fp16 2-way split of one float4 (verified R11): v*scale = h + l*2^-11.
__device__ __forceinline__ void cvt_store2(float4 v, float scale,
                                           uint32_t hB, uint32_t lB, int row, int c4) {
    v.x *= scale; v.y *= scale; v.z *= scale; v.w *= scale;
    uint32_t h01, h23;
    asm("cvt.rn.f16x2.f32 %0, %1, %2;" : "=r"(h01) : "f"(v.y), "f"(v.x));
    asm("cvt.rn.f16x2.f32 %0, %1, %2;" : "=r"(h23) : "f"(v.w), "f"(v.z));
    float h0, h1, h2, h3;
    asm("{.reg .b16 lo,hi; mov.b32 {lo,hi}, %2; cvt.f32.f16 %0, lo; cvt.f32.f16 %1, hi;}"
        : "=f"(h0), "=f"(h1) : "r"(h01));
    asm("{.reg .b16 lo,hi; mov.b32 {lo,hi}, %2; cvt.f32.f16 %0, lo; cvt.f32.f16 %1, hi;}"
        : "=f"(h2), "=f"(h3) : "r"(h23));
    float r0 = (v.x - h0) * LO_SCALE, r1 = (v.y - h1) * LO_SCALE;
    float r2 = (v.z - h2) * LO_SCALE, r3 = (v.w - h3) * LO_SCALE;
    uint32_t l01, l23;
    asm("cvt.rn.f16x2.f32 %0, %1, %2;" : "=r"(l01) : "f"(r1), "f"(r0));
    asm("cvt.rn.f16x2.f32 %0, %1, %2;" : "=r"(l23) : "f"(r3), "f"(r2));
    uint32_t off = swz((uint32_t)(row * 128 + c4 * 8));
    asm volatile("st.shared.v2.b32 [%0], {%1,%2};" :: "r"(hB + off), "r"(h01), "r"(h23));
    asm volatile("st.shared.v2.b32 [%0], {%1,%2};" :: "r"(lB + off), "r"(l01), "r"(l23));
}

__device__ __forceinline__ void load_chunk(const float* __restrict__ A,
                                           const float* __restrict__ W,
                                           int m0, int chunk, int tid,
                                           float4* ra, float4* rb) {
    const int k0 = chunk * KC;
    #pragma unroll
    for (int i = 0; i < 4; i++) {
        int idx = tid + i * THREADS;
        int row = idx >> 4;
        int c4  = idx & 15;
        ra[i] = *reinterpret_cast<const float4*>(A + (size_t)(m0 + row) * H_DIM + k0 + c4 * 4);
    }
    #pragma unroll
    for (int i = 0; i < 2; i++) {
        int idx = tid + i * THREADS;
        int row = idx >> 4;
        int c4  = idx & 15;
        rb[i] = *reinterpret_cast<const float4*>(W + (size_t)row * H_DIM + k0 + c4 * 4);
    }
}

__device__ __forceinline__ void ldsm4(uint32_t addr, uint32_t& r0, uint32_t& r1,
                                      uint32_t& r2, uint32_t& r3) {
    asm volatile("ldmatrix.sync.aligned.m8n8.x4.shared.b16 {%0,%1,%2,%3}, [%4];"
                 : "=r"(r0), "=r"(r1), "=r"(r2), "=r"(r3) : "r"(addr));
}

__device__ __forceinline__ void mma16816(float* d, const uint32_t* a, const uint32_t* b) {
    asm volatile(
        "mma.sync.aligned.m16n8k16.row.col.f32.f16.f16.f32 "
        "{%0,%1,%2,%3}, {%4,%5,%6,%7}, {%8,%9}, {%0,%1,%2,%3};"
        : "+f"(d[0]), "+f"(d[1]), "+f"(d[2]), "+f"(d[3])
        : "r"(a[0]), "r"(a[1]), "r"(a[2]), "r"(a[3]), "r"(b[0]), "r"(b[1]));
}

// ---------------------------------------------------------------------------
// R11 HMMA fp16 2-way-split GEMM (verified, 122us) + fused top-8 epilogue.
// ---------------------------------------------------------------------------
__global__ __launch_bounds__(THREADS, 1) void router_fused(
    const float* __restrict__ A, const float* __restrict__ W,
    float* __restrict__ logits, float* __restrict__ scores,
    float* __restrict__ indices)
{
    extern __shared__ char dsm[];
    const uint32_t base = (s2u(dsm) + 127u) & ~127u;
    const uint32_t stage_base[2] = { base, base + STAGE_SZ };

    const int tid  = threadIdx.x;
    const int warp = tid >> 5;
    const int lane = tid & 31;
    const int m0   = blockIdx.x * BM;

    const int rg = warp >> 1;     // row group: rows rg*16 .. rg*16+15
    const int eh = warp & 1;      // expert half: experts eh*32 .. eh*32+31

    const uint32_t a_off0 = (uint32_t)((rg * 16 + (lane & 15)) * 128 + (lane >> 4) * 16);
    const uint32_t b_off0 = (uint32_t)((((lane >> 4) << 3) + (lane & 7)) * 128 +
                                       ((lane >> 3) & 1) * 16 + eh * 2 * 2048);

    float accM[4][4];
    #pragma unroll
    for (int nt = 0; nt < 4; nt++)
        #pragma unroll
        for (int j = 0; j < 4; j++) accM[nt][j] = 0.f;

    float4 na[4], nb[2];
    load_chunk(A, W, m0, 0, tid, na, nb);

    for (int chunk = 0; chunk < NCHUNK; ++chunk) {
        const int s = chunk & 1;
        const uint32_t aH = stage_base[s];
        const uint32_t aL = aH + A_PL;
        const uint32_t bH = aL + A_PL;
        const uint32_t bL = bH + B_PL;

        #pragma unroll
        for (int i = 0; i < 4; i++) {
            int idx = tid + i * THREADS;
            cvt_store2(na[i], 1.0f, aH, aL, idx >> 4, idx & 15);
        }
        #pragma unroll
        for (int i = 0; i < 2; i++) {
            int idx = tid + i * THREADS;
            cvt_store2(nb[i], W_SCALE, bH, bL, idx >> 4, idx & 15);
        }
        if (chunk + 1 < NCHUNK) load_chunk(A, W, m0, chunk + 1, tid, na, nb);
        __syncthreads();

        float accS0[4][4], accS1[4][4];
        #pragma unroll
        for (int nt = 0; nt < 4; nt++)
            #pragma unroll
            for (int j = 0; j < 4; j++) { accS0[nt][j] = 0.f; accS1[nt][j] = 0.f; }

        #pragma unroll
        for (int ks = 0; ks < 4; ks++) {
            const uint32_t ka = (uint32_t)(ks * 32);
            uint32_t ah[4], al[4];
            ldsm4(aH + swz(a_off0 + ka), ah[0], ah[1], ah[2], ah[3]);
            ldsm4(aL + swz(a_off0 + ka), al[0], al[1], al[2], al[3]);

            uint32_t bf[4][2];
            const uint32_t bo0 = swz(b_off0 + ka);
            const uint32_t bo1 = swz(b_off0 + 2048 + ka);

            ldsm4(bH + bo0, bf[0][0], bf[0][1], bf[1][0], bf[1][1]);
            ldsm4(bH + bo1, bf[2][0], bf[2][1], bf[3][0], bf[3][1]);
            #pragma unroll
            for (int nt = 0; nt < 4; nt++) mma16816(accS0[nt], ah, bf[nt]);
            #pragma unroll
            for (int nt = 0; nt < 4; nt++) mma16816(accS1[nt], al, bf[nt]);

            ldsm4(bL + bo0, bf[0][0], bf[0][1], bf[1][0], bf[1][1]);
            ldsm4(bL + bo1, bf[2][0], bf[2][1], bf[3][0], bf[3][1]);
            #pragma unroll
            for (int nt = 0; nt < 4; nt++) mma16816(accS1[nt], ah, bf[nt]);
        }

        #pragma unroll
        for (int nt = 0; nt < 4; nt++)
            #pragma unroll
            for (int j = 0; j < 4; j++)
                accM[nt][j] += fmaf(accS1[nt][j], LO_FOLD, accS0[nt][j]);
    }

    // ---- epilogue: logits to gmem + smem tile for fused topk ----
    const uint32_t LT = base;     // alias stage 0 (free after last chunk)
    __syncthreads();              // all ldsm of last chunk done before overwrite
    {
        const int lr0 = rg * 16 + (lane >> 2);
        const int col = eh * 32 + (lane & 3) * 2;
        #pragma unroll
        for (int nt = 0; nt < 4; nt++) {
            float v0 = accM[nt][0] * OUT_SCALE, v1 = accM[nt][1] * OUT_SCALE;
            float v2 = accM[nt][2] * OUT_SCALE, v3 = accM[nt][3] * OUT_SCALE;
            const int c = nt * 8 + col;
            *reinterpret_cast<float2*>(logits + (size_t)(m0 + lr0) * E_DIM + c) =
                make_float2(v0, v1);
            *reinterpret_cast<float2*>(logits + (size_t)(m0 + lr0 + 8) * E_DIM + c) =
                make_float2(v2, v3);
            asm volatile("st.shared.v2.b32 [%0], {%1,%2};"
                         :: "r"(LT + (uint32_t)((lr0 * LT_STR + c) * 4)),
                            "r"(__float_as_uint(v0)), "r"(__float_as_uint(v1)));
            asm volatile("st.shared.v2.b32 [%0], {%1,%2};"
                         :: "r"(LT + (uint32_t)(((lr0 + 8) * LT_STR + c) * 4)),
                            "r"(__float_as_uint(v2)), "r"(__float_as_uint(v3)));
        }
    }
    __syncthreads();

    // ---- fused top-8 + renormalized softmax (verified R12 epilogue) ----
    #pragma unroll 1
    for (int t = 0; t < 8; t++) {
        const int row = warp * 8 + t;
        const uint32_t lg = LT + (uint32_t)(row * LT_STR * 4);
        float v0 = lds_f32(lg + (uint32_t)(lane * 4));
        float v1 = lds_f32(lg + (uint32_t)((lane + 32) * 4));

        float topv[TOPK];
        int   topi[TOPK];
        #pragma unroll
        for (int r = 0; r < TOPK; r++) {
            bool p   = (v0 >= v1);
            float lv = p ? v0 : v1;
            int   li = p ? lane : lane + 32;
            #pragma unroll
            for (int off = 16; off > 0; off >>= 1) {
                float ov = __shfl_xor_sync(0xffffffffu, lv, off);
                int   oi = __shfl_xor_sync(0xffffffffu, li, off);
                if (ov > lv || (ov == lv && oi < li)) { lv = ov; li = oi; }
            }
            topv[r] = lv; topi[r] = li;
            if (li == lane)           v0 = -INFINITY;
            else if (li == lane + 32) v1 = -INFINITY;
        }
        if (lane == 0) {
            const float m = topv[0];
            float e[TOPK], ssum = 0.f;
            #pragma unroll
            for (int r = 0; r < TOPK; r++) { e[r] = expf(topv[r] - m); ssum += e[r]; }
            const float inv = 1.f / ssum;
            #pragma unroll
            for (int r = 0; r < TOPK; r++) {
                scores [(size_t)(m0 + row) * TOPK + r] = e[r] * inv;
                indices[(size_t)(m0 + row) * TOPK + r] = (float)topi[r];
            }
        }
    }
}

// ---------------------------------------------------------------------------
extern "C" void kernel_launch(void* const* d_in, const int* in_sizes, int n_in,
                              void* d_out, int out_size)
{
    const float* hs = (const float*)d_in[0];   // hidden_states [T, 4096]
    const float* w  = (const float*)d_in[1];   // weight        [64, 4096]
    const int T = in_sizes[0] / H_DIM;

    float* out     = (float*)d_out;
    float* logits  = out;
    float* scores  = out + (size_t)T * E_DIM;
    float* indices = scores + (size_t)T * TOPK;

    cudaFuncSetAttribute(router_fused, cudaFuncAttributeMaxDynamicSharedMemorySize, DYN_SZ);
    router_fused<<<T / BM, THREADS, DYN_SZ>>>(hs, w, logits, scores, indices);
}

// round 14
// speedup vs baseline: 2.4358x; 1.0696x over previous
#include <cuda_runtime.h>
#include <cuda_fp16.h>
#include <math.h>
#include <stdint.h>

#define H_DIM 4096
#define E_DIM 64
#define TOPK  8
#define BM    64                  // tokens per CTA
#define KC    64                  // K per chunk (= one accumulation segment)
#define NCHUNK (H_DIM / KC)       // 64
#define THREADS 256

#define A_PL  (BM * KC * 2)       // 8192 B per A fp16 plane
#define B_PL  (E_DIM * KC * 2)    // 8192 B per B fp16 plane
#define STAGE_SZ (2 * A_PL + 2 * B_PL)   // 32768 B
#define TILE_SZ (2 * STAGE_SZ)           // 65536 B
#define DYN_SZ (TILE_SZ + 256)

#define W_SCALE   64.0f           // W pre-scale (2^6, exact)
#define OUT_SCALE 0.015625f       // 2^-6
#define LO_SCALE  2048.0f         // lo-plane pre-scale (2^11, exact)
#define LO_FOLD   4.8828125e-4f   // 2^-11

__device__ __forceinline__ uint32_t s2u(const void* p) {
    uint32_t a;
    asm("{ .reg .u64 t; cvta.to.shared.u64 t, %1; cvt.u32.u64 %0, t; }" : "=r"(a) : "l"(p));
    return a;
}
__device__ __forceinline__ uint32_t swz(uint32_t b) { return b ^ ((b >> 3) & 0x70); }

// fp16 2-way split of one float4 (verified R11): v*scale = h + l*2^-11.
__device__ __forceinline__ void cvt_store2(float4 v, float scale,
                                           uint32_t hB, uint32_t lB, int row, int c4) {
    v.x *= scale; v.y *= scale; v.z *= scale; v.w *= scale;
    uint32_t h01, h23;
    asm("cvt.rn.f16x2.f32 %0, %1, %2;" : "=r"(h01) : "f"(v.y), "f"(v.x));
    asm("cvt.rn.f16x2.f32 %0, %1, %2;" : "=r"(h23) : "f"(v.w), "f"(v.z));
    float h0, h1, h2, h3;
    asm("{.reg .b16 lo,hi; mov.b32 {lo,hi}, %2; cvt.f32.f16 %0, lo; cvt.f32.f16 %1, hi;}"
        : "=f"(h0), "=f"(h1) : "r"(h01));
    asm("{.reg .b16 lo,hi; mov.b32 {lo,hi}, %2; cvt.f32.f16 %0, lo; cvt.f32.f16 %1, hi;}"
        : "=f"(h2), "=f"(h3) : "r"(h23));
    float r0 = (v.x - h0) * LO_SCALE, r1 = (v.y - h1) * LO_SCALE;
    float r2 = (v.z - h2) * LO_SCALE, r3 = (v.w - h3) * LO_SCALE;
    uint32_t l01, l23;
    asm("cvt.rn.f16x2.f32 %0, %1, %2;" : "=r"(l01) : "f"(r1), "f"(r0));
    asm("cvt.rn.f16x2.f32 %0, %1, %2;" : "=r"(l23) : "f"(r3), "f"(r2));
    uint32_t off = swz((uint32_t)(row * 128 + c4 * 8));
    asm volatile("st.shared.v2.b32 [%0], {%1,%2};" :: "r"(hB + off), "r"(h01), "r"(h23));
    asm volatile("st.shared.v2.b32 [%0], {%1,%2};" :: "r"(lB + off), "r"(l01), "r"(l23));
}

__device__ __forceinline__ void load_chunk(const float* __restrict__ A,
                                           const float* __restrict__ W,
                                           int m0, int chunk, int tid,
                                           float4* ra, float4* rb) {
    const int k0 = chunk * KC;
    #pragma unroll
    for (int i = 0; i < 4; i++) {                  // 4*256 = 1024 = 64 rows x 16
        int idx = tid + i * THREADS;
        int row = idx >> 4;
        int c4  = idx & 15;
        ra[i] = *reinterpret_cast<const float4*>(A + (size_t)(m0 + row) * H_DIM + k0 + c4 * 4);
    }
    #pragma unroll
    for (int i = 0; i < 4; i++) {                  // 4*256 = 1024 = 64 rows x 16
        int idx = tid + i * THREADS;
        int row = idx >> 4;
        int c4  = idx & 15;
        rb[i] = *reinterpret_cast<const float4*>(W + (size_t)row * H_DIM + k0 + c4 * 4);
    }
}

__device__ __forceinline__ void ldsm4(uint32_t addr, uint32_t& r0, uint32_t& r1,
                                      uint32_t& r2, uint32_t& r3) {
    asm volatile("ldmatrix.sync.aligned.m8n8.x4.shared.b16 {%0,%1,%2,%3}, [%4];"
                 : "=r"(r0), "=r"(r1), "=r"(r2), "=r"(r3) : "r"(addr));
}

__device__ __forceinline__ void mma16816(float* d, const uint32_t* a, const uint32_t* b) {
    asm volatile(
        "mma.sync.aligned.m16n8k16.row.col.f32.f16.f16.f32 "
        "{%0,%1,%2,%3}, {%4,%5,%6,%7}, {%8,%9}, {%0,%1,%2,%3};"
        : "+f"(d[0]), "+f"(d[1]), "+f"(d[2]), "+f"(d[3])
        : "r"(a[0]), "r"(a[1]), "r"(a[2]), "r"(a[3]), "r"(b[0]), "r"(b[1]));
}

// ---------------------------------------------------------------------------
// HMMA fp16 2-way-split GEMM (numerics == R11), BM=64 / 256 threads,
// 2 CTAs per SM for cross-CTA latency hiding.
// ---------------------------------------------------------------------------
__global__ __launch_bounds__(THREADS, 2) void router_gemm_tc(
    const float* __restrict__ A, const float* __restrict__ W,
    float* __restrict__ logits)
{
    extern __shared__ char dsm[];
    const uint32_t base = (s2u(dsm) + 127u) & ~127u;
    const uint32_t stage_base[2] = { base, base + STAGE_SZ };

    const int tid  = threadIdx.x;
    const int warp = tid >> 5;
    const int lane = tid & 31;
    const int m0   = blockIdx.x * BM;

    const int rg = warp >> 1;     // row group 0..3: rows rg*16 .. rg*16+15
    const int eh = warp & 1;      // expert half: experts eh*32 .. eh*32+31

    const uint32_t a_off0 = (uint32_t)((rg * 16 + (lane & 15)) * 128 + (lane >> 4) * 16);
    const uint32_t b_off0 = (uint32_t)((((lane >> 4) << 3) + (lane & 7)) * 128 +
                                       ((lane >> 3) & 1) * 16 + eh * 2 * 2048);

    float accM[4][4];
    #pragma unroll
    for (int nt = 0; nt < 4; nt++)
        #pragma unroll
        for (int j = 0; j < 4; j++) accM[nt][j] = 0.f;

    float4 na[4], nb[4];
    load_chunk(A, W, m0, 0, tid, na, nb);

    for (int chunk = 0; chunk < NCHUNK; ++chunk) {
        const int s = chunk & 1;
        const uint32_t aH = stage_base[s];
        const uint32_t aL = aH + A_PL;
        const uint32_t bH = aL + A_PL;
        const uint32_t bL = bH + B_PL;

        #pragma unroll
        for (int i = 0; i < 4; i++) {
            int idx = tid + i * THREADS;
            cvt_store2(na[i], 1.0f, aH, aL, idx >> 4, idx & 15);
        }
        #pragma unroll
        for (int i = 0; i < 4; i++) {
            int idx = tid + i * THREADS;
            cvt_store2(nb[i], W_SCALE, bH, bL, idx >> 4, idx & 15);
        }
        if (chunk + 1 < NCHUNK) load_chunk(A, W, m0, chunk + 1, tid, na, nb);
        __syncthreads();

        float accS0[4][4], accS1[4][4];
        #pragma unroll
        for (int nt = 0; nt < 4; nt++)
            #pragma unroll
            for (int j = 0; j < 4; j++) { accS0[nt][j] = 0.f; accS1[nt][j] = 0.f; }

        #pragma unroll
        for (int ks = 0; ks < 4; ks++) {
            const uint32_t ka = (uint32_t)(ks * 32);
            uint32_t ah[4], al[4];
            ldsm4(aH + swz(a_off0 + ka), ah[0], ah[1], ah[2], ah[3]);
            ldsm4(aL + swz(a_off0 + ka), al[0], al[1], al[2], al[3]);

            uint32_t bf[4][2];
            const uint32_t bo0 = swz(b_off0 + ka);
            const uint32_t bo1 = swz(b_off0 + 2048 + ka);

            ldsm4(bH + bo0, bf[0][0], bf[0][1], bf[1][0], bf[1][1]);
            ldsm4(bH + bo1, bf[2][0], bf[2][1], bf[3][0], bf[3][1]);
            #pragma unroll
            for (int nt = 0; nt < 4; nt++) mma16816(accS0[nt], ah, bf[nt]);
            #pragma unroll
            for (int nt = 0; nt < 4; nt++) mma16816(accS1[nt], al, bf[nt]);

            ldsm4(bL + bo0, bf[0][0], bf[0][1], bf[1][0], bf[1][1]);
            ldsm4(bL + bo1, bf[2][0], bf[2][1], bf[3][0], bf[3][1]);
            #pragma unroll
            for (int nt = 0; nt < 4; nt++) mma16816(accS1[nt], ah, bf[nt]);
        }

        #pragma unroll
        for (int nt = 0; nt < 4; nt++)
            #pragma unroll
            for (int j = 0; j < 4; j++)
                accM[nt][j] += fmaf(accS1[nt][j], LO_FOLD, accS0[nt][j]);
    }

    // epilogue: undo W pre-scale (exact *2^-6)
    const int r0  = m0 + rg * 16 + (lane >> 2);
    const int col = eh * 32 + (lane & 3) * 2;
    #pragma unroll
    for (int nt = 0; nt < 4; nt++) {
        float* d0 = logits + (size_t)r0 * E_DIM + nt * 8 + col;
        float* d1 = logits + (size_t)(r0 + 8) * E_DIM + nt * 8 + col;
        *reinterpret_cast<float2*>(d0) =
            make_float2(accM[nt][0] * OUT_SCALE, accM[nt][1] * OUT_SCALE);
        *reinterpret_cast<float2*>(d1) =
            make_float2(accM[nt][2] * OUT_SCALE, accM[nt][3] * OUT_SCALE);
    }
}

// ---------------------------------------------------------------------------
// Kernel 2: top-8 + renormalized softmax scores (unchanged, verified)
// ---------------------------------------------------------------------------
__global__ __launch_bounds__(256) void topk_kernel(
    const float* __restrict__ logits,
    float* __restrict__ scores,
    float* __restrict__ indices, int T)
{
    const int warp = (int)((blockIdx.x * blockDim.x + threadIdx.x) >> 5);
    const int lane = threadIdx.x & 31;
    if (warp >= T) return;

    const float* lg = logits + (size_t)warp * E_DIM;
    float v0 = lg[lane];
    float v1 = lg[lane + 32];

    float topv[TOPK];
    int   topi[TOPK];

    #pragma unroll
    for (int r = 0; r < TOPK; r++) {
        bool p   = (v0 >= v1);
        float lv = p ? v0 : v1;
        int   li = p ? lane : lane + 32;
        #pragma unroll
        for (int off = 16; off > 0; off >>= 1) {
            float ov = __shfl_xor_sync(0xffffffffu, lv, off);
            int   oi = __shfl_xor_sync(0xffffffffu, li, off);
            if (ov > lv || (ov == lv && oi < li)) { lv = ov; li = oi; }
        }
        topv[r] = lv; topi[r] = li;
        if (li == lane)           v0 = -INFINITY;
        else if (li == lane + 32) v1 = -INFINITY;
    }

    if (lane == 0) {
        const float m = topv[0];
        float e[TOPK], s = 0.f;
        #pragma unroll
        for (int r = 0; r < TOPK; r++) { e[r] = expf(topv[r] - m); s += e[r]; }
        const float inv = 1.f / s;
        #pragma unroll
        for (int r = 0; r < TOPK; r++) {
            scores [(size_t)warp * TOPK + r] = e[r] * inv;
            indices[(size_t)warp * TOPK + r] = (float)topi[r];
        }
    }
}

// ---------------------------------------------------------------------------
extern "C" void kernel_launch(void* const* d_in, const int* in_sizes, int n_in,
                              void* d_out, int out_size)
{
    const float* hs = (const float*)d_in[0];   // hidden_states [T, 4096]
    const float* w  = (const float*)d_in[1];   // weight        [64, 4096]
    const int T = in_sizes[0] / H_DIM;

    float* out     = (float*)d_out;
    float* logits  = out;
    float* scores  = out + (size_t)T * E_DIM;
    float* indices = scores + (size_t)T * TOPK;

    cudaFuncSetAttribute(router_gemm_tc, cudaFuncAttributeMaxDynamicSharedMemorySize, DYN_SZ);
    router_gemm_tc<<<T / BM, THREADS, DYN_SZ>>>(hs, w, logits);

    const int warps_per_block = 256 / 32;
    const int grid = (T + warps_per_block - 1) / warps_per_block;
    topk_kernel<<<grid, 256>>>(logits, scores, indices, T);
}

// round 15
// speedup vs baseline: 2.5629x; 1.0522x over previous
#include <cuda_runtime.h>
#include <cuda_fp16.h>
#include <math.h>
#include <stdint.h>

#define H_DIM 4096
#define E_DIM 64
#define TOPK  8
#define BM    128                 // tokens per CTA
#define KC    64                  // K per chunk (= one accumulation segment)
#define NCHUNK (H_DIM / KC)       // 64
#define THREADS 256               // 8 warps: 4 row-groups x 2 expert-halves

#define A_PL  (BM * KC * 2)       // 16384 B per A fp16 plane
#define B_PL  (E_DIM * KC * 2)    // 8192  B per B fp16 plane
#define STAGE_SZ (2 * A_PL + 2 * B_PL)   // 49152 B
#define TILE_SZ (2 * STAGE_SZ)           // 98304 B
#define DYN_SZ (TILE_SZ + 256)

#define W_SCALE   64.0f           // W pre-scale (2^6, exact)
#define OUT_SCALE 0.015625f       // 2^-6
#define LO_SCALE  2048.0f         // lo-plane pre-scale (2^11, exact)
#define LO_FOLD   4.8828125e-4f   // 2^-11

__device__ __forceinline__ uint32_t s2u(const void* p) {
    uint32_t a;
    asm("{ .reg .u64 t; cvta.to.shared.u64 t, %1; cvt.u32.u64 %0, t; }" : "=r"(a) : "l"(p));
    return a;
}
__device__ __forceinline__ uint32_t swz(uint32_t b) { return b ^ ((b >> 3) & 0x70); }

// fp16 2-way split of one float4 (verified R11): v*scale = h + l*2^-11.
__device__ __forceinline__ void cvt_store2(float4 v, float scale,
                                           uint32_t hB, uint32_t lB, int row, int c4) {
    v.x *= scale; v.y *= scale; v.z *= scale; v.w *= scale;
    uint32_t h01, h23;
    asm("cvt.rn.f16x2.f32 %0, %1, %2;" : "=r"(h01) : "f"(v.y), "f"(v.x));
    asm("cvt.rn.f16x2.f32 %0, %1, %2;" : "=r"(h23) : "f"(v.w), "f"(v.z));
    float h0, h1, h2, h3;
    asm("{.reg .b16 lo,hi; mov.b32 {lo,hi}, %2; cvt.f32.f16 %0, lo; cvt.f32.f16 %1, hi;}"
        : "=f"(h0), "=f"(h1) : "r"(h01));
    asm("{.reg .b16 lo,hi; mov.b32 {lo,hi}, %2; cvt.f32.f16 %0, lo; cvt.f32.f16 %1, hi;}"
        : "=f"(h2), "=f"(h3) : "r"(h23));
    float r0 = (v.x - h0) * LO_SCALE, r1 = (v.y - h1) * LO_SCALE;
    float r2 = (v.z - h2) * LO_SCALE, r3 = (v.w - h3) * LO_SCALE;
    uint32_t l01, l23;
    asm("cvt.rn.f16x2.f32 %0, %1, %2;" : "=r"(l01) : "f"(r1), "f"(r0));
    asm("cvt.rn.f16x2.f32 %0, %1, %2;" : "=r"(l23) : "f"(r3), "f"(r2));
    uint32_t off = swz((uint32_t)(row * 128 + c4 * 8));
    asm volatile("st.shared.v2.b32 [%0], {%1,%2};" :: "r"(hB + off), "r"(h01), "r"(h23));
    asm volatile("st.shared.v2.b32 [%0], {%1,%2};" :: "r"(lB + off), "r"(l01), "r"(l23));
}

__device__ __forceinline__ void load_chunk(const float* __restrict__ A,
                                           const float* __restrict__ W,
                                           int m0, int chunk, int tid,
                                           float4* ra, float4* rb) {
    const int k0 = chunk * KC;
    #pragma unroll
    for (int i = 0; i < 8; i++) {                  // 8*256 = 2048 = 128 rows x 16
        int idx = tid + i * THREADS;
        int row = idx >> 4;
        int c4  = idx & 15;
        ra[i] = *reinterpret_cast<const float4*>(A + (size_t)(m0 + row) * H_DIM + k0 + c4 * 4);
    }
    #pragma unroll
    for (int i = 0; i < 4; i++) {                  // 4*256 = 1024 = 64 rows x 16
        int idx = tid + i * THREADS;
        int row = idx >> 4;
        int c4  = idx & 15;
        rb[i] = *reinterpret_cast<const float4*>(W + (size_t)row * H_DIM + k0 + c4 * 4);
    }
}

__device__ __forceinline__ void ldsm4(uint32_t addr, uint32_t& r0, uint32_t& r1,
                                      uint32_t& r2, uint32_t& r3) {
    asm volatile("ldmatrix.sync.aligned.m8n8.x4.shared.b16 {%0,%1,%2,%3}, [%4];"
                 : "=r"(r0), "=r"(r1), "=r"(r2), "=r"(r3) : "r"(addr));
}

__device__ __forceinline__ void mma16816(float* d, const uint32_t* a, const uint32_t* b) {
    asm volatile(
        "mma.sync.aligned.m16n8k16.row.col.f32.f16.f16.f32 "
        "{%0,%1,%2,%3}, {%4,%5,%6,%7}, {%8,%9}, {%0,%1,%2,%3};"
        : "+f"(d[0]), "+f"(d[1]), "+f"(d[2]), "+f"(d[3])
        : "r"(a[0]), "r"(a[1]), "r"(a[2]), "r"(a[3]), "r"(b[0]), "r"(b[1]));
}

// ---------------------------------------------------------------------------
// HMMA fp16 2-way-split GEMM (numerics == R11), 32x32 warp tiles:
// 8 warps = 4 row-groups(32 rows) x 2 expert-halves(32 experts).
// Cuts LDSM traffic 33% vs 16x32 tiling (B redundancy 8 -> 4).
// ---------------------------------------------------------------------------
__global__ __launch_bounds__(THREADS, 1) void router_gemm_tc(
    const float* __restrict__ A, const float* __restrict__ W,
    float* __restrict__ logits)
{
    extern __shared__ char dsm[];
    const uint32_t base = (s2u(dsm) + 127u) & ~127u;
    const uint32_t stage_base[2] = { base, base + STAGE_SZ };

    const int tid  = threadIdx.x;
    const int warp = tid >> 5;
    const int lane = tid & 31;
    const int m0   = blockIdx.x * BM;

    const int rg = warp >> 1;     // row group 0..3: rows rg*32 .. rg*32+31
    const int eh = warp & 1;      // expert half: experts eh*32 .. eh*32+31

    // A fragment base for m-tile 0 (rows rg*32 .. +15); m-tile 1 adds 16*128 B
    const uint32_t a_off0 = (uint32_t)((rg * 32 + (lane & 15)) * 128 + (lane >> 4) * 16);
    const uint32_t b_off0 = (uint32_t)((((lane >> 4) << 3) + (lane & 7)) * 128 +
                                       ((lane >> 3) & 1) * 16 + eh * 2 * 2048);

    float accM[2][4][4];
    #pragma unroll
    for (int mt = 0; mt < 2; mt++)
        #pragma unroll
        for (int nt = 0; nt < 4; nt++)
            #pragma unroll
            for (int j = 0; j < 4; j++) accM[mt][nt][j] = 0.f;

    float4 na[8], nb[4];
    load_chunk(A, W, m0, 0, tid, na, nb);

    for (int chunk = 0; chunk < NCHUNK; ++chunk) {
        const int s = chunk & 1;
        const uint32_t aH = stage_base[s];
        const uint32_t aL = aH + A_PL;
        const uint32_t bH = aL + A_PL;
        const uint32_t bL = bH + B_PL;

        #pragma unroll
        for (int i = 0; i < 8; i++) {
            int idx = tid + i * THREADS;
            cvt_store2(na[i], 1.0f, aH, aL, idx >> 4, idx & 15);
        }
        #pragma unroll
        for (int i = 0; i < 4; i++) {
            int idx = tid + i * THREADS;
            cvt_store2(nb[i], W_SCALE, bH, bL, idx >> 4, idx & 15);
        }
        if (chunk + 1 < NCHUNK) load_chunk(A, W, m0, chunk + 1, tid, na, nb);
        __syncthreads();

        float accS0[2][4][4], accS1[2][4][4];
        #pragma unroll
        for (int mt = 0; mt < 2; mt++)
            #pragma unroll
            for (int nt = 0; nt < 4; nt++)
                #pragma unroll
                for (int j = 0; j < 4; j++) { accS0[mt][nt][j] = 0.f; accS1[mt][nt][j] = 0.f; }

        #pragma unroll
        for (int ks = 0; ks < 4; ks++) {
            const uint32_t ka = (uint32_t)(ks * 32);
            uint32_t ah[2][4], al[2][4];
            #pragma unroll
            for (int mt = 0; mt < 2; mt++) {
                const uint32_t ao = a_off0 + (uint32_t)(mt * 16 * 128) + ka;
                ldsm4(aH + swz(ao), ah[mt][0], ah[mt][1], ah[mt][2], ah[mt][3]);
                ldsm4(aL + swz(ao), al[mt][0], al[mt][1], al[mt][2], al[mt][3]);
            }

            uint32_t bh[4][2], bl[4][2];
            const uint32_t bo0 = swz(b_off0 + ka);
            const uint32_t bo1 = swz(b_off0 + 2048 + ka);
            ldsm4(bH + bo0, bh[0][0], bh[0][1], bh[1][0], bh[1][1]);
            ldsm4(bH + bo1, bh[2][0], bh[2][1], bh[3][0], bh[3][1]);
            ldsm4(bL + bo0, bl[0][0], bl[0][1], bl[1][0], bl[1][1]);
            ldsm4(bL + bo1, bl[2][0], bl[2][1], bl[3][0], bl[3][1]);

            #pragma unroll
            for (int mt = 0; mt < 2; mt++) {
                #pragma unroll
                for (int nt = 0; nt < 4; nt++) mma16816(accS0[mt][nt], ah[mt], bh[nt]);
                #pragma unroll
                for (int nt = 0; nt < 4; nt++) mma16816(accS1[mt][nt], al[mt], bh[nt]);
                #pragma unroll
                for (int nt = 0; nt < 4; nt++) mma16816(accS1[mt][nt], ah[mt], bl[nt]);
            }
        }

        #pragma unroll
        for (int mt = 0; mt < 2; mt++)
            #pragma unroll
            for (int nt = 0; nt < 4; nt++)
                #pragma unroll
                for (int j = 0; j < 4; j++)
                    accM[mt][nt][j] += fmaf(accS1[mt][nt][j], LO_FOLD, accS0[mt][nt][j]);
    }

    // epilogue: undo W pre-scale (exact *2^-6)
    #pragma unroll
    for (int mt = 0; mt < 2; mt++) {
        const int r0  = m0 + rg * 32 + mt * 16 + (lane >> 2);
        const int col = eh * 32 + (lane & 3) * 2;
        #pragma unroll
        for (int nt = 0; nt < 4; nt++) {
            float* d0 = logits + (size_t)r0 * E_DIM + nt * 8 + col;
            float* d1 = logits + (size_t)(r0 + 8) * E_DIM + nt * 8 + col;
            *reinterpret_cast<float2*>(d0) =
                make_float2(accM[mt][nt][0] * OUT_SCALE, accM[mt][nt][1] * OUT_SCALE);
            *reinterpret_cast<float2*>(d1) =
                make_float2(accM[mt][nt][2] * OUT_SCALE, accM[mt][nt][3] * OUT_SCALE);
        }
    }
}

// ---------------------------------------------------------------------------
// Kernel 2: top-8 + renormalized softmax scores (unchanged, verified)
// ---------------------------------------------------------------------------
__global__ __launch_bounds__(256) void topk_kernel(
    const float* __restrict__ logits,
    float* __restrict__ scores,
    float* __restrict__ indices, int T)
{
    const int warp = (int)((blockIdx.x * blockDim.x + threadIdx.x) >> 5);
    const int lane = threadIdx.x & 31;
    if (warp >= T) return;

    const float* lg = logits + (size_t)warp * E_DIM;
    float v0 = lg[lane];
    float v1 = lg[lane + 32];

    float topv[TOPK];
    int   topi[TOPK];

    #pragma unroll
    for (int r = 0; r < TOPK; r++) {
        bool p   = (v0 >= v1);
        float lv = p ? v0 : v1;
        int   li = p ? lane : lane + 32;
        #pragma unroll
        for (int off = 16; off > 0; off >>= 1) {
            float ov = __shfl_xor_sync(0xffffffffu, lv, off);
            int   oi = __shfl_xor_sync(0xffffffffu, li, off);
            if (ov > lv || (ov == lv && oi < li)) { lv = ov; li = oi; }
        }
        topv[r] = lv; topi[r] = li;
        if (li == lane)           v0 = -INFINITY;
        else if (li == lane + 32) v1 = -INFINITY;
    }

    if (lane == 0) {
        const float m = topv[0];
        float e[TOPK], s = 0.f;
        #pragma unroll
        for (int r = 0; r < TOPK; r++) { e[r] = expf(topv[r] - m); s += e[r]; }
        const float inv = 1.f / s;
        #pragma unroll
        for (int r = 0; r < TOPK; r++) {
            scores [(size_t)warp * TOPK + r] = e[r] * inv;
            indices[(size_t)warp * TOPK + r] = (float)topi[r];
        }
    }
}

// ---------------------------------------------------------------------------
extern "C" void kernel_launch(void* const* d_in, const int* in_sizes, int n_in,
                              void* d_out, int out_size)
{
    const float* hs = (const float*)d_in[0];   // hidden_states [T, 4096]
    const float* w  = (const float*)d_in[1];   // weight        [64, 4096]
    const int T = in_sizes[0] / H_DIM;

    float* out     = (float*)d_out;
    float* logits  = out;
    float* scores  = out + (size_t)T * E_DIM;
    float* indices = scores + (size_t)T * TOPK;

    cudaFuncSetAttribute(router_gemm_tc, cudaFuncAttributeMaxDynamicSharedMemorySize, DYN_SZ);
    router_gemm_tc<<<T / BM, THREADS, DYN_SZ>>>(hs, w, logits);

    const int warps_per_block = 256 / 32;
    const int grid = (T + warps_per_block - 1) / warps_per_block;
    topk_kernel<<<grid, 256>>>(logits, scores, indices, T);
}